// round 14
// baseline (speedup 1.0000x reference)
#include <cuda_runtime.h>
#include <cstdint>
#include <math.h>

// Problem dims (fixed)
#define SEQ   1024
#define DH    64
#define HEADS 64          // bz*16
#define MD    1024        // model_dim
#define ND    2048        // model_dim * n_scale
#define MROWS 4096        // bz*seq

// Scratch (allocation-free rule: device globals)
__device__ float    g_rp[(size_t)MROWS * ND];            // 32 MB
__device__ float    g_ctot[(size_t)HEADS * SEQ * 128];   // 32 MB: ctx1/ctx2 interleaved
__device__ float    g_scores[(size_t)HEADS * SEQ * SEQ]; // 256 MB: raw scaled scores
__device__ uint32_t g_r32[(size_t)MROWS * MD];           // 16 MB: tf32(r)
__device__ uint32_t g_wr32[(size_t)ND * MD];             //  8 MB: tf32(Wr)
__device__ uint32_t g_wf32[(size_t)ND * ND];             // 16 MB: tf32(Wf)
__device__ uint2    g_ksp[(size_t)HEADS * SEQ * DH];     // 32 MB: hi/lo split of k
__device__ uint2    g_vsp[(size_t)HEADS * SEQ * DH];     // 32 MB: hi/lo split of v

// ---------------------------------------------------------------------------
// Helpers
// ---------------------------------------------------------------------------
__device__ __forceinline__ uint32_t f2tf32(float x) {
    uint32_t r;
    asm("cvt.rna.tf32.f32 %0, %1;" : "=r"(r) : "f"(x));
    return r;
}

__device__ __forceinline__ void hilo(float x, uint32_t& h, uint32_t& l) {
    h = f2tf32(x);
    l = f2tf32(x - __uint_as_float(h));
}

__device__ __forceinline__ void mma_tf32(float* c, const uint32_t* a, const uint32_t* b) {
    asm volatile(
        "mma.sync.aligned.m16n8k8.row.col.f32.tf32.tf32.f32 "
        "{%0,%1,%2,%3},{%4,%5,%6,%7},{%8,%9},{%0,%1,%2,%3};"
        : "+f"(c[0]), "+f"(c[1]), "+f"(c[2]), "+f"(c[3])
        : "r"(a[0]), "r"(a[1]), "r"(a[2]), "r"(a[3]), "r"(b[0]), "r"(b[1]));
}

__device__ __forceinline__ void cp16(void* smem, const void* gmem) {
    uint32_t s = (uint32_t)__cvta_generic_to_shared(smem);
    asm volatile("cp.async.ca.shared.global [%0], [%1], 16;" :: "r"(s), "l"(gmem));
}
#define CP_COMMIT() asm volatile("cp.async.commit_group;")
#define CP_WAIT1()  asm volatile("cp.async.wait_group 1;")
#define CP_WAIT0()  asm volatile("cp.async.wait_group 0;")

// ---------------------------------------------------------------------------
// Pre-pass kernels: tf32 conversion and hi/lo splitting (one-time, streaming)
// ---------------------------------------------------------------------------
__global__ void conv_tf32_kernel(const float* __restrict__ src, uint32_t* __restrict__ dst, int n4)
{
    const int i = blockIdx.x * blockDim.x + threadIdx.x;
    if (i < n4) {
        float4 v = ((const float4*)src)[i];
        ((uint4*)dst)[i] = make_uint4(f2tf32(v.x), f2tf32(v.y), f2tf32(v.z), f2tf32(v.w));
    }
}

__global__ void split_hilo_kernel(const float* __restrict__ src, uint2* __restrict__ dst, int n4)
{
    const int i = blockIdx.x * blockDim.x + threadIdx.x;
    if (i < n4) {
        float4 v = ((const float4*)src)[i];
        uint32_t h0, l0, h1, l1, h2, l2, h3, l3;
        hilo(v.x, h0, l0); hilo(v.y, h1, l1);
        hilo(v.z, h2, l2); hilo(v.w, h3, l3);
        uint4* d = (uint4*)(dst + (size_t)i * 4);
        d[0] = make_uint4(h0, l0, h1, l1);
        d[1] = make_uint4(h2, l2, h3, l3);
    }
}

// ---------------------------------------------------------------------------
// TF32 GEMM on PRE-CONVERTED operands (no cvt in the loop).
// C = A B^T + bias (+ addend). BM=BN=128, BK=16, 256 threads, warp tile 32x64.
// cp.async 3-stage pipeline.
// ---------------------------------------------------------------------------
#define GSTR 20
#define GEMM_STAGE (128 * GSTR)
#define GEMM_SMEM (3 * 2 * GEMM_STAGE * 4)   // 61,440 B

__global__ void __launch_bounds__(256, 2) gemm_tf32(
    const uint32_t* __restrict__ A, const uint32_t* __restrict__ B,
    const float* __restrict__ bias, const float* __restrict__ addend,
    float* __restrict__ C, int M, int N, int K)
{
    extern __shared__ uint32_t gsm[];
    uint32_t* As = gsm;                       // [3][GEMM_STAGE]
    uint32_t* Bs = gsm + 3 * GEMM_STAGE;      // [3][GEMM_STAGE]

    const int tid  = threadIdx.x;
    const int warp = tid >> 5, lane = tid & 31;
    const int wm = (warp >> 1) * 32;
    const int wn = (warp & 1) * 64;
    const int m0 = blockIdx.y * 128, n0 = blockIdx.x * 128;
    const int g  = lane >> 2;
    const int tg = lane & 3;

    float acc[2][8][4];
#pragma unroll
    for (int i = 0; i < 2; i++)
#pragma unroll
        for (int j = 0; j < 8; j++)
#pragma unroll
            for (int r = 0; r < 4; r++) acc[i][j][r] = 0.f;

    auto load_stage = [&](int s, int k0) {
#pragma unroll
        for (int i = 0; i < 2; i++) {
            const int idx = tid + 256 * i;
            const int row = idx >> 2;
            const int cq  = (idx & 3) * 4;
            cp16(&As[s * GEMM_STAGE + row * GSTR + cq], A + (size_t)(m0 + row) * K + k0 + cq);
            cp16(&Bs[s * GEMM_STAGE + row * GSTR + cq], B + (size_t)(n0 + row) * K + k0 + cq);
        }
    };

    const int ntiles = K / 16;
    load_stage(0, 0);  CP_COMMIT();
    load_stage(1, 16); CP_COMMIT();

    for (int t = 0; t < ntiles; t++) {
        if (t + 1 < ntiles) { CP_WAIT1(); } else { CP_WAIT0(); }
        __syncthreads();
        if (t + 2 < ntiles) {
            load_stage((t + 2) % 3, (t + 2) * 16);
            CP_COMMIT();
        }

        const uint32_t* Ab = As + (t % 3) * GEMM_STAGE;
        const uint32_t* Bb = Bs + (t % 3) * GEMM_STAGE;
#pragma unroll
        for (int ks = 0; ks < 16; ks += 8) {
            uint32_t afrag[2][4], bfrag[8][2];
#pragma unroll
            for (int mi = 0; mi < 2; mi++) {
                const int row = wm + mi * 16 + g;
                afrag[mi][0] = Ab[row * GSTR + ks + tg];
                afrag[mi][1] = Ab[(row + 8) * GSTR + ks + tg];
                afrag[mi][2] = Ab[row * GSTR + ks + tg + 4];
                afrag[mi][3] = Ab[(row + 8) * GSTR + ks + tg + 4];
            }
#pragma unroll
            for (int ni = 0; ni < 8; ni++) {
                const int col = wn + ni * 8 + g;
                bfrag[ni][0] = Bb[col * GSTR + ks + tg];
                bfrag[ni][1] = Bb[col * GSTR + ks + tg + 4];
            }
#pragma unroll
            for (int mi = 0; mi < 2; mi++)
#pragma unroll
                for (int ni = 0; ni < 8; ni++)
                    mma_tf32(acc[mi][ni], afrag[mi], bfrag[ni]);
        }
        __syncthreads();
    }

#pragma unroll
    for (int mi = 0; mi < 2; mi++) {
#pragma unroll
        for (int ni = 0; ni < 8; ni++) {
            const int m = m0 + wm + mi * 16 + g;
            const int n = n0 + wn + ni * 8 + tg * 2;
            const float bx = bias[n], by = bias[n + 1];
            float2 v0 = make_float2(acc[mi][ni][0] + bx, acc[mi][ni][1] + by);
            float2 v1 = make_float2(acc[mi][ni][2] + bx, acc[mi][ni][3] + by);
            if (addend) {
                float2 d0 = *(const float2*)(addend + (size_t)m * N + n);
                float2 d1 = *(const float2*)(addend + (size_t)(m + 8) * N + n);
                v0.x += d0.x; v0.y += d0.y; v1.x += d1.x; v1.y += d1.y;
            }
            *(float2*)(C + (size_t)m * N + n) = v0;
            *(float2*)(C + (size_t)(m + 8) * N + n) = v1;
        }
    }
}

// ---------------------------------------------------------------------------
// Tensor-core attention, tf32x3 scores. K/V come PRE-SPLIT (hi,lo) from gmem.
// Tile copy: each row = 64 uint2 = 32 uint4; 2 threads/row x 16 uint4 each.
// Phase 1: scores -> g_scores + streaming (m,l) (3 independent accumulators).
// Phase 2: p from cached scores; PV with pv3 ? x3 : x2 precision.
// ---------------------------------------------------------------------------
#define ASTR 68
#define ATTN_SMEM (128 * ASTR * 4 + 128 * ASTR * 8)   // sQ + uint2 KV = 104,448 B

__global__ void __launch_bounds__(256, 2)
attn_mma(const float* __restrict__ Qbase, int q_head_stride, int q_row_stride,
         const uint2* __restrict__ Ksp, const uint2* __restrict__ Vsp,
         float* __restrict__ scores,
         float* __restrict__ attn_out,   // nullptr for pass 2
         float* __restrict__ ctx_out, int ctx_off, int pv3)
{
    extern __shared__ char smraw[];
    float* sQ  = (float*)smraw;                        // [128][ASTR] floats
    uint2* sKV = (uint2*)(smraw + 128 * ASTR * 4);     // [128][ASTR] (hi,lo) pairs

    const int H   = blockIdx.y;
    const int q0  = blockIdx.x * 128;
    const int tid = threadIdx.x;
    const int w   = tid >> 5, lane = tid & 31;
    const int g   = lane >> 2, tg = lane & 3;
    const int wq  = w * 16;

    const float* Qh = Qbase + (size_t)H * q_head_stride + (size_t)q0 * q_row_stride;
    const uint2* Kh = Ksp + (size_t)H * (SEQ * DH);
    const uint2* Vh = Vsp + (size_t)H * (SEQ * DH);
    float* Sh = scores + (size_t)H * SEQ * SEQ + (size_t)q0 * SEQ;

    const int lr  = tid >> 1;            // loader row 0..127
    const int lc0 = (tid & 1) * 32;      // loader col base: floats for Q, uint2 for KV

    // ---- load Q tile (128x64 fp32) into smem, coalesced ----
#pragma unroll
    for (int i = 0; i < 8; i++) {
        float4 v = *(const float4*)(Qh + (size_t)lr * q_row_stride + lc0 + i * 4);
        *(float4*)&sQ[lr * ASTR + lc0 + i * 4] = v;
    }
    __syncthreads();

    // ---- extract warp's Q fragments (rows wq+g, wq+g+8), hi/lo split ----
    uint32_t qh[8][4], ql[8][4];
#pragma unroll
    for (int kc = 0; kc < 8; kc++) {
        const int col = 8 * kc + tg;
        hilo(sQ[(wq + g) * ASTR + col],         qh[kc][0], ql[kc][0]);
        hilo(sQ[(wq + g + 8) * ASTR + col],     qh[kc][1], ql[kc][1]);
        hilo(sQ[(wq + g) * ASTR + col + 4],     qh[kc][2], ql[kc][2]);
        hilo(sQ[(wq + g + 8) * ASTR + col + 4], qh[kc][3], ql[kc][3]);
    }

    float mloc[2] = {-INFINITY, -INFINITY};
    float lloc[2] = {0.f, 0.f};

    // ================= Phase 1: scores + streaming stats =================
    for (int kb = 0; kb < 8; kb++) {
        __syncthreads();
        // copy pre-split K tile: row = 32 uint4; 2 threads/row x 16 uint4
        {
            const uint4* src = (const uint4*)(Kh + (size_t)(kb * 128 + lr) * DH + lc0);
            uint4* dst = (uint4*)(sKV + lr * ASTR + lc0);
#pragma unroll
            for (int i = 0; i < 16; i++) dst[i] = src[i];
        }
        __syncthreads();

#pragma unroll 1
        for (int nt = 0; nt < 16; nt++) {
            float aHH[4] = {0.f, 0.f, 0.f, 0.f};
            float aHL[4] = {0.f, 0.f, 0.f, 0.f};
            float aLH[4] = {0.f, 0.f, 0.f, 0.f};
#pragma unroll
            for (int kc = 0; kc < 8; kc++) {
                const uint2 b0 = sKV[(8 * nt + g) * ASTR + 8 * kc + tg];
                const uint2 b1 = sKV[(8 * nt + g) * ASTR + 8 * kc + tg + 4];
                uint32_t bh[2] = {b0.x, b1.x};
                uint32_t bl[2] = {b0.y, b1.y};
                mma_tf32(aHH, qh[kc], bh);
                mma_tf32(aHL, qh[kc], bl);
                mma_tf32(aLH, ql[kc], bh);
            }
            float acc[4];
#pragma unroll
            for (int j = 0; j < 4; j++)
                acc[j] = ((aHL[j] + aLH[j]) + aHH[j]) * 8.f;   // scale = sqrt(d)

            *(float2*)(Sh + (size_t)(wq + g) * SEQ + kb * 128 + 8 * nt + 2 * tg)
                = make_float2(acc[0], acc[1]);
            *(float2*)(Sh + (size_t)(wq + g + 8) * SEQ + kb * 128 + 8 * nt + 2 * tg)
                = make_float2(acc[2], acc[3]);

            {
                const float mx = fmaxf(acc[0], acc[1]);
                const float nm = fmaxf(mloc[0], mx);
                lloc[0] = lloc[0] * __expf(mloc[0] - nm) + __expf(acc[0] - nm) + __expf(acc[1] - nm);
                mloc[0] = nm;
            }
            {
                const float mx = fmaxf(acc[2], acc[3]);
                const float nm = fmaxf(mloc[1], mx);
                lloc[1] = lloc[1] * __expf(mloc[1] - nm) + __expf(acc[2] - nm) + __expf(acc[3] - nm);
                mloc[1] = nm;
            }
        }
    }

    // ---- merge (m,l) across the quad ----
    float invl[2];
#pragma unroll
    for (int i = 0; i < 2; i++) {
#pragma unroll
        for (int off = 1; off <= 2; off <<= 1) {
            const float om = __shfl_xor_sync(0xffffffffu, mloc[i], off);
            const float ol = __shfl_xor_sync(0xffffffffu, lloc[i], off);
            const float nm = fmaxf(mloc[i], om);
            lloc[i] = lloc[i] * __expf(mloc[i] - nm) + ol * __expf(om - nm);
            mloc[i] = nm;
        }
        invl[i] = 1.f / lloc[i];
    }

    // ================= Phase 2: probabilities + PV =================
    float ctx[8][4];
#pragma unroll
    for (int nt = 0; nt < 8; nt++)
#pragma unroll
        for (int j = 0; j < 4; j++) ctx[nt][j] = 0.f;

    for (int kb = 0; kb < 8; kb++) {
        __syncthreads();
        // copy pre-split V tile: 2 threads/row x 16 uint4
        {
            const uint4* src = (const uint4*)(Vh + (size_t)(kb * 128 + lr) * DH + lc0);
            uint4* dst = (uint4*)(sKV + lr * ASTR + lc0);
#pragma unroll
            for (int i = 0; i < 16; i++) dst[i] = src[i];
        }
        __syncthreads();

#pragma unroll 1
        for (int kc = 0; kc < 16; kc++) {
            const int cbase = kb * 128 + 8 * kc;
            const float s0 = Sh[(size_t)(wq + g) * SEQ + cbase + tg];
            const float s1 = Sh[(size_t)(wq + g + 8) * SEQ + cbase + tg];
            const float s2 = Sh[(size_t)(wq + g) * SEQ + cbase + tg + 4];
            const float s3 = Sh[(size_t)(wq + g + 8) * SEQ + cbase + tg + 4];
            const float p0 = __expf(s0 - mloc[0]) * invl[0];
            const float p1 = __expf(s1 - mloc[1]) * invl[1];
            const float p2 = __expf(s2 - mloc[0]) * invl[0];
            const float p3 = __expf(s3 - mloc[1]) * invl[1];

            if (attn_out) {
                float* ao = attn_out + ((size_t)H * SEQ + q0) * SEQ;
                ao[(size_t)(wq + g) * SEQ + cbase + tg]         = p0;
                ao[(size_t)(wq + g + 8) * SEQ + cbase + tg]     = p1;
                ao[(size_t)(wq + g) * SEQ + cbase + tg + 4]     = p2;
                ao[(size_t)(wq + g + 8) * SEQ + cbase + tg + 4] = p3;
            }

            uint32_t ph[4], pl[4];
            hilo(p0, ph[0], pl[0]);
            hilo(p1, ph[1], pl[1]);
            hilo(p2, ph[2], pl[2]);
            hilo(p3, ph[3], pl[3]);

#pragma unroll
            for (int nt = 0; nt < 8; nt++) {
                const uint2 v0 = sKV[(8 * kc + tg) * ASTR + 8 * nt + g];
                const uint2 v1 = sKV[(8 * kc + tg + 4) * ASTR + 8 * nt + g];
                uint32_t vh[2] = {v0.x, v1.x};
                uint32_t vl[2] = {v0.y, v1.y};
                mma_tf32(ctx[nt], ph, vh);
                mma_tf32(ctx[nt], ph, vl);
                if (pv3) mma_tf32(ctx[nt], pl, vh);
            }
        }
    }

    // ---- write ctx into interleaved ctot (row stride 128) ----
#pragma unroll
    for (int nt = 0; nt < 8; nt++) {
        const int c = ctx_off + 8 * nt + 2 * tg;
        *(float2*)(ctx_out + ((size_t)H * SEQ + q0 + wq + g) * 128 + c)
            = make_float2(ctx[nt][0], ctx[nt][1]);
        *(float2*)(ctx_out + ((size_t)H * SEQ + q0 + wq + g + 8) * 128 + c)
            = make_float2(ctx[nt][2], ctx[nt][3]);
    }
}

// ---------------------------------------------------------------------------
// Row LayerNorm over ND=2048
// ---------------------------------------------------------------------------
__global__ void ln_kernel(const float* __restrict__ X, const float* __restrict__ gamma,
                          const float* __restrict__ beta, float* __restrict__ Y)
{
    __shared__ float red[64];
    const int row = blockIdx.x;
    const float* x = X + (size_t)row * ND;
    float sum = 0.f, sq = 0.f;
    for (int i = threadIdx.x; i < ND; i += blockDim.x) {
        const float v = x[i];
        sum += v; sq += v * v;
    }
#pragma unroll
    for (int off = 16; off; off >>= 1) {
        sum += __shfl_xor_sync(0xffffffffu, sum, off);
        sq  += __shfl_xor_sync(0xffffffffu, sq, off);
    }
    const int warp = threadIdx.x >> 5, lane = threadIdx.x & 31;
    if (lane == 0) { red[warp] = sum; red[warp + 32] = sq; }
    __syncthreads();
    if (warp == 0) {
        sum = (lane < 8) ? red[lane] : 0.f;
        sq  = (lane < 8) ? red[lane + 32] : 0.f;
#pragma unroll
        for (int off = 4; off; off >>= 1) {
            sum += __shfl_xor_sync(0xffffffffu, sum, off);
            sq  += __shfl_xor_sync(0xffffffffu, sq, off);
        }
        if (lane == 0) { red[0] = sum; red[1] = sq; }
    }
    __syncthreads();
    const float mu  = red[0] * (1.f / ND);
    const float var = red[1] * (1.f / ND) - mu * mu;
    const float inv = rsqrtf(var + 1e-5f);
    float* y = Y + (size_t)row * ND;
    for (int i = threadIdx.x; i < ND; i += blockDim.x)
        y[i] = (x[i] - mu) * inv * gamma[i] + beta[i];
}

// ---------------------------------------------------------------------------
extern "C" void kernel_launch(void* const* d_in, const int* in_sizes, int n_in,
                              void* d_out, int out_size)
{
    const float* k_in  = (const float*)d_in[0];
    const float* v_in  = (const float*)d_in[1];
    const float* q_in  = (const float*)d_in[2];
    const float* r_in  = (const float*)d_in[3];
    const float* Wr    = (const float*)d_in[4];
    const float* br    = (const float*)d_in[5];
    const float* Wf    = (const float*)d_in[6];
    const float* bf    = (const float*)d_in[7];
    const float* gamma = (const float*)d_in[8];
    const float* beta  = (const float*)d_in[9];

    float* out      = (float*)d_out;
    float* y_out    = out;
    float* attn_out = out + (size_t)MROWS * ND;

    float*    rp;     cudaGetSymbolAddress((void**)&rp, g_rp);
    float*    ctot;   cudaGetSymbolAddress((void**)&ctot, g_ctot);
    float*    scores; cudaGetSymbolAddress((void**)&scores, g_scores);
    uint32_t* r32;    cudaGetSymbolAddress((void**)&r32, g_r32);
    uint32_t* wr32;   cudaGetSymbolAddress((void**)&wr32, g_wr32);
    uint32_t* wf32;   cudaGetSymbolAddress((void**)&wf32, g_wf32);
    uint2*    ksp;    cudaGetSymbolAddress((void**)&ksp, g_ksp);
    uint2*    vsp;    cudaGetSymbolAddress((void**)&vsp, g_vsp);

    cudaFuncSetAttribute(attn_mma, cudaFuncAttributeMaxDynamicSharedMemorySize, ATTN_SMEM);
    cudaFuncSetAttribute(gemm_tf32, cudaFuncAttributeMaxDynamicSharedMemorySize, GEMM_SMEM);

    // 0) pre-passes: tf32 conversions + hi/lo splits (streaming)
    {
        const int T = 256;
        int n4;
        n4 = (MROWS * MD) / 4;  conv_tf32_kernel<<<(n4 + T - 1) / T, T>>>(r_in, r32, n4);
        n4 = (ND * MD) / 4;     conv_tf32_kernel<<<(n4 + T - 1) / T, T>>>(Wr, wr32, n4);
        n4 = (ND * ND) / 4;     conv_tf32_kernel<<<(n4 + T - 1) / T, T>>>(Wf, wf32, n4);
        n4 = (HEADS * SEQ * DH) / 4;
        split_hilo_kernel<<<(n4 + T - 1) / T, T>>>(k_in, ksp, n4);
        split_hilo_kernel<<<(n4 + T - 1) / T, T>>>(v_in, vsp, n4);
    }

    // 1) rp = r @ Wr^T + br   (pre-converted operands)
    dim3 g1(ND / 128, MROWS / 128);
    gemm_tf32<<<g1, 256, GEMM_SMEM>>>(r32, wr32, br, nullptr, rp, MROWS, ND, MD);

    // 2) pass 1: attn1 -> d_out, ctx1 -> ctot[..,0:64]  (full tf32x3 PV)
    dim3 ga(SEQ / 128, HEADS);
    attn_mma<<<ga, 256, ATTN_SMEM>>>(q_in, SEQ * DH, DH, ksp, vsp, scores, attn_out, ctot, 0, 1);

    // 3) pass 2: queries = ctx1 (stride 128), ctx2 -> ctot[..,64:128]  (PV x2)
    attn_mma<<<ga, 256, ATTN_SMEM>>>(ctot, SEQ * 128, 128, ksp, vsp, scores, nullptr, ctot, 64, 0);

    // 3b) convert ctot to tf32 in place (rewritten fully by attention each replay)
    {
        const int T = 256;
        const int n4 = (HEADS * SEQ * 128) / 4;
        conv_tf32_kernel<<<(n4 + T - 1) / T, T>>>(ctot, (uint32_t*)ctot, n4);
    }

    // 4) x = ctot @ Wf^T + bf + rp
    gemm_tf32<<<g1, 256, GEMM_SMEM>>>((const uint32_t*)ctot, wf32, bf, rp, rp, MROWS, ND, ND);

    // 5) y = LayerNorm(x)
    ln_kernel<<<MROWS, 256>>>(rp, gamma, beta, y_out);
}

// round 17
// speedup vs baseline: 1.7108x; 1.7108x over previous
#include <cuda_runtime.h>
#include <cuda_fp16.h>
#include <cstdint>
#include <math.h>

// Problem dims (fixed)
#define SEQ   1024
#define DH    64
#define HEADS 64          // bz*16
#define MD    1024        // model_dim
#define ND    2048        // model_dim * n_scale
#define MROWS 4096        // bz*seq

// Scratch (allocation-free rule: device globals)
__device__ float    g_rp[(size_t)MROWS * ND];            // 32 MB
__device__ float    g_ctot[(size_t)HEADS * SEQ * 128];   // 32 MB ctx1/ctx2 interleaved
__device__ float    g_scores[(size_t)HEADS * SEQ * SEQ]; // 256 MB raw scaled scores
__device__ __half   g_rh[(size_t)MROWS * MD];            //  8 MB fp16(r)
__device__ __half   g_wrh[(size_t)ND * MD];              //  4 MB fp16(Wr)
__device__ __half   g_wfh[(size_t)ND * ND];              //  8 MB fp16(Wf)
__device__ __half   g_ctoth[(size_t)HEADS * SEQ * 128];  // 16 MB fp16(ctot)
__device__ uint2    g_k2[(size_t)HEADS * SEQ * (DH / 2)];   // 16 MB K (hi2,lo2) d-pairs
__device__ uint2    g_vt2[(size_t)HEADS * DH * (SEQ / 2)];  // 16 MB V^T (hi2,lo2) key-pairs

// ---------------------------------------------------------------------------
// Helpers
// ---------------------------------------------------------------------------
__device__ __forceinline__ void hilo2(float2 v, uint32_t& h, uint32_t& l) {
    __half2 hh = __floats2half2_rn(v.x, v.y);
    float2 hf = __half22float2(hh);
    __half2 ll = __floats2half2_rn(v.x - hf.x, v.y - hf.y);
    h = *reinterpret_cast<uint32_t*>(&hh);
    l = *reinterpret_cast<uint32_t*>(&ll);
}

__device__ __forceinline__ uint32_t h2pack(float a, float b) {
    __half2 hh = __floats2half2_rn(a, b);
    return *reinterpret_cast<uint32_t*>(&hh);
}

__device__ __forceinline__ void mma_f16(float* c, const uint32_t* a, const uint32_t* b) {
    asm volatile(
        "mma.sync.aligned.m16n8k16.row.col.f32.f16.f16.f32 "
        "{%0,%1,%2,%3},{%4,%5,%6,%7},{%8,%9},{%0,%1,%2,%3};"
        : "+f"(c[0]), "+f"(c[1]), "+f"(c[2]), "+f"(c[3])
        : "r"(a[0]), "r"(a[1]), "r"(a[2]), "r"(a[3]), "r"(b[0]), "r"(b[1]));
}

__device__ __forceinline__ void ldsm_x4(uint32_t* r, uint32_t saddr) {
    asm volatile("ldmatrix.sync.aligned.m8n8.x4.shared.b16 {%0,%1,%2,%3}, [%4];"
        : "=r"(r[0]), "=r"(r[1]), "=r"(r[2]), "=r"(r[3]) : "r"(saddr));
}
__device__ __forceinline__ void ldsm_x2(uint32_t* r, uint32_t saddr) {
    asm volatile("ldmatrix.sync.aligned.m8n8.x2.shared.b16 {%0,%1}, [%2];"
        : "=r"(r[0]), "=r"(r[1]) : "r"(saddr));
}

__device__ __forceinline__ void cp16(void* smem, const void* gmem) {
    uint32_t s = (uint32_t)__cvta_generic_to_shared(smem);
    asm volatile("cp.async.ca.shared.global [%0], [%1], 16;" :: "r"(s), "l"(gmem));
}
#define CP_COMMIT() asm volatile("cp.async.commit_group;")
#define CP_WAIT1()  asm volatile("cp.async.wait_group 1;")
#define CP_WAIT0()  asm volatile("cp.async.wait_group 0;")

// ---------------------------------------------------------------------------
// Pre-pass kernels
// ---------------------------------------------------------------------------
__global__ void conv_half_kernel(const float* __restrict__ src, __half* __restrict__ dst, int n4)
{
    const int i = blockIdx.x * blockDim.x + threadIdx.x;
    if (i < n4) {
        float4 v = ((const float4*)src)[i];
        uint2 o;
        o.x = h2pack(v.x, v.y);
        o.y = h2pack(v.z, v.w);
        ((uint2*)dst)[i] = o;
    }
}

// K: [H][1024][64] fp32 -> [H][1024][32] uint2 (hi2, lo2) over d-pairs
__global__ void split_k_kernel(const float* __restrict__ src, uint2* __restrict__ dst, int n4)
{
    const int i = blockIdx.x * blockDim.x + threadIdx.x;
    if (i < n4) {
        float4 v = ((const float4*)src)[i];
        uint32_t h0, l0, h1, l1;
        hilo2(make_float2(v.x, v.y), h0, l0);
        hilo2(make_float2(v.z, v.w), h1, l1);
        ((uint4*)dst)[i] = make_uint4(h0, l0, h1, l1);
    }
}

// V: [H][1024][64] fp32 -> VT: [H][64][512] uint2 (hi2, lo2) over key-pairs
__global__ void split_vt_kernel(const float* __restrict__ v, uint2* __restrict__ vt)
{
    const int idx = blockIdx.x * blockDim.x + threadIdx.x;  // H*512*64
    const int d  = idx & 63;
    const int kp = (idx >> 6) & 511;
    const int H  = idx >> 15;
    const float a = v[((size_t)H * SEQ + 2 * kp) * DH + d];
    const float b = v[((size_t)H * SEQ + 2 * kp + 1) * DH + d];
    uint32_t h, l;
    hilo2(make_float2(a, b), h, l);
    vt[((size_t)H * DH + d) * (SEQ / 2) + kp] = make_uint2(h, l);
}

// ---------------------------------------------------------------------------
// fp16 GEMM (m16n8k16 + ldmatrix), cp.async 3-stage pipeline.
// C = A B^T + bias (+ addend). BM=BN=128, BK=32, 256 threads, warp tile 32x64.
// ---------------------------------------------------------------------------
#define STRH 40                      // halves per row (32 + 8 pad) = 80 B
#define HSTAGE (128 * STRH)          // 5120 halves per matrix stage
#define GEMM_SMEM (3 * 2 * HSTAGE * 2)   // 61,440 B

__global__ void __launch_bounds__(256, 2) gemm_f16(
    const __half* __restrict__ A, const __half* __restrict__ B,
    const float* __restrict__ bias, const float* __restrict__ addend,
    float* __restrict__ C, int M, int N, int K)
{
    extern __shared__ __half hsm[];
    __half* As = hsm;
    __half* Bs = hsm + 3 * HSTAGE;

    const int tid  = threadIdx.x;
    const int warp = tid >> 5, lane = tid & 31;
    const int wm = (warp >> 1) * 32;
    const int wn = (warp & 1) * 64;
    const int m0 = blockIdx.y * 128, n0 = blockIdx.x * 128;
    const int g  = lane >> 2;
    const int tg = lane & 3;
    const uint32_t smem_u32 = (uint32_t)__cvta_generic_to_shared(hsm);

    float acc[2][8][4];
#pragma unroll
    for (int i = 0; i < 2; i++)
#pragma unroll
        for (int j = 0; j < 8; j++)
#pragma unroll
            for (int r = 0; r < 4; r++) acc[i][j][r] = 0.f;

    auto load_stage = [&](int s, int k0) {
#pragma unroll
        for (int i = 0; i < 2; i++) {
            const int idx = tid + 256 * i;       // 0..511
            const int row = idx >> 2;
            const int c   = (idx & 3) * 8;       // halves (16 B)
            cp16(&As[s * HSTAGE + row * STRH + c], A + (size_t)(m0 + row) * K + k0 + c);
            cp16(&Bs[s * HSTAGE + row * STRH + c], B + (size_t)(n0 + row) * K + k0 + c);
        }
    };

    // ldmatrix lane-address components
    const int lr   = lane & 7;            // row within 8-row tile
    const int lt   = lane >> 3;           // tile id 0..3 (x4)
    const int arow = ((lt & 1) ? lr + 8 : lr);
    const int acol = (lt >= 2) ? 8 : 0;
    const int bcol = ((lane >> 3) & 1) * 8;   // x2: lanes 0-7 col 0, 8-15 col 8

    const int ntiles = K / 32;
    load_stage(0, 0);  CP_COMMIT();
    load_stage(1, 32); CP_COMMIT();

    for (int t = 0; t < ntiles; t++) {
        if (t + 1 < ntiles) { CP_WAIT1(); } else { CP_WAIT0(); }
        __syncthreads();
        if (t + 2 < ntiles) {
            load_stage((t + 2) % 3, (t + 2) * 32);
            CP_COMMIT();
        }

        const uint32_t Abase = smem_u32 + (uint32_t)((t % 3) * HSTAGE) * 2;
        const uint32_t Bbase = smem_u32 + (uint32_t)(3 * HSTAGE + (t % 3) * HSTAGE) * 2;
#pragma unroll
        for (int ks = 0; ks < 32; ks += 16) {
            uint32_t af[2][4], bf[8][2];
#pragma unroll
            for (int mi = 0; mi < 2; mi++)
                ldsm_x4(af[mi], Abase + (uint32_t)((wm + mi * 16 + arow) * STRH + ks + acol) * 2);
#pragma unroll
            for (int ni = 0; ni < 8; ni++)
                ldsm_x2(bf[ni], Bbase + (uint32_t)((wn + ni * 8 + lr) * STRH + ks + bcol) * 2);
#pragma unroll
            for (int mi = 0; mi < 2; mi++)
#pragma unroll
                for (int ni = 0; ni < 8; ni++)
                    mma_f16(acc[mi][ni], af[mi], bf[ni]);
        }
        __syncthreads();
    }

#pragma unroll
    for (int mi = 0; mi < 2; mi++) {
#pragma unroll
        for (int ni = 0; ni < 8; ni++) {
            const int m = m0 + wm + mi * 16 + g;
            const int n = n0 + wn + ni * 8 + tg * 2;
            const float bx = bias[n], by = bias[n + 1];
            float2 v0 = make_float2(acc[mi][ni][0] + bx, acc[mi][ni][1] + by);
            float2 v1 = make_float2(acc[mi][ni][2] + bx, acc[mi][ni][3] + by);
            if (addend) {
                float2 d0 = *(const float2*)(addend + (size_t)m * N + n);
                float2 d1 = *(const float2*)(addend + (size_t)(m + 8) * N + n);
                v0.x += d0.x; v0.y += d0.y; v1.x += d1.x; v1.y += d1.y;
            }
            *(float2*)(C + (size_t)m * N + n) = v0;
            *(float2*)(C + (size_t)(m + 8) * N + n) = v1;
        }
    }
}

// ---------------------------------------------------------------------------
// fp16x3 tensor-core attention (scores fp16x3 ~ 2^-22; PV x3 pass1 / x2 pass2).
// K pre-split [H][key][32 d-pairs] uint2(hi2,lo2); V pre-split+transposed
// [H][d][512 key-pairs]. Q fragments loaded directly from gmem per warp.
// Phase 1: scores -> g_scores + streaming (m,l). Phase 2: p + PV.
// ---------------------------------------------------------------------------
#define KSTR 36   // uint2 per K-tile row (32 + 4 pad)  -> conflict-free LDS.64
#define VSTR 68   // uint2 per VT-tile row (64 + 4 pad) -> conflict-free LDS.64
#define ATTN_SMEM (128 * KSTR * 8)   // 36,864 B >= 64*VSTR*8 = 34,816 B

__global__ void __launch_bounds__(256, 2)
attn_f16(const float* __restrict__ Qbase, int q_head_stride, int q_row_stride,
         const uint2* __restrict__ K2, const uint2* __restrict__ VT2,
         float* __restrict__ scores,
         float* __restrict__ attn_out,   // nullptr for pass 2
         float* __restrict__ ctx_out, int ctx_off, int pv3)
{
    extern __shared__ uint2 sKV2[];   // K tile [128][KSTR] or VT tile [64][VSTR]

    const int H   = blockIdx.y;
    const int q0  = blockIdx.x * 128;
    const int tid = threadIdx.x;
    const int w   = tid >> 5, lane = tid & 31;
    const int g   = lane >> 2, tg = lane & 3;
    const int wq  = w * 16;

    const uint2* Kh  = K2 + (size_t)H * (SEQ * (DH / 2));
    const uint2* VTh = VT2 + (size_t)H * (DH * (SEQ / 2));
    float* Sh = scores + (size_t)H * SEQ * SEQ + (size_t)q0 * SEQ;

    // ---- Q fragments straight from gmem, hi/lo split (once per block) ----
    const float* Qr0 = Qbase + (size_t)H * q_head_stride + (size_t)(q0 + wq + g) * q_row_stride;
    const float* Qr1 = Qbase + (size_t)H * q_head_stride + (size_t)(q0 + wq + g + 8) * q_row_stride;
    uint32_t qh[4][4], ql[4][4];
#pragma unroll
    for (int kc = 0; kc < 4; kc++) {
        const int c = 16 * kc + 2 * tg;
        hilo2(*(const float2*)(Qr0 + c),     qh[kc][0], ql[kc][0]);
        hilo2(*(const float2*)(Qr1 + c),     qh[kc][1], ql[kc][1]);
        hilo2(*(const float2*)(Qr0 + c + 8), qh[kc][2], ql[kc][2]);
        hilo2(*(const float2*)(Qr1 + c + 8), qh[kc][3], ql[kc][3]);
    }

    float mloc[2] = {-INFINITY, -INFINITY};
    float lloc[2] = {0.f, 0.f};

    // ================= Phase 1: scores + streaming stats =================
    const int klr = tid >> 1;            // K-copy row 0..127
    const int khf = tid & 1;             // half-row selector
    for (int kb = 0; kb < 8; kb++) {
        __syncthreads();
        {   // copy K tile: row = 32 uint2 = 16 uint4; 2 threads/row x 8 uint4
            const uint4* src = (const uint4*)(Kh + (size_t)(kb * 128 + klr) * 32) + khf * 8;
            uint4* dst = (uint4*)(sKV2 + klr * KSTR) + khf * 8;
#pragma unroll
            for (int i = 0; i < 8; i++) dst[i] = src[i];
        }
        __syncthreads();

#pragma unroll 1
        for (int nt = 0; nt < 16; nt++) {
            float aHH[4] = {0.f, 0.f, 0.f, 0.f};
            float aHL[4] = {0.f, 0.f, 0.f, 0.f};
            float aLH[4] = {0.f, 0.f, 0.f, 0.f};
#pragma unroll
            for (int kc = 0; kc < 4; kc++) {
                const uint2 b0 = sKV2[(8 * nt + g) * KSTR + 8 * kc + tg];
                const uint2 b1 = sKV2[(8 * nt + g) * KSTR + 8 * kc + tg + 4];
                uint32_t bh[2] = {b0.x, b1.x};
                uint32_t bl[2] = {b0.y, b1.y};
                mma_f16(aHH, qh[kc], bh);
                mma_f16(aHL, qh[kc], bl);
                mma_f16(aLH, ql[kc], bh);
            }
            float acc[4];
#pragma unroll
            for (int j = 0; j < 4; j++)
                acc[j] = ((aHL[j] + aLH[j]) + aHH[j]) * 8.f;   // scale = sqrt(d)

            *(float2*)(Sh + (size_t)(wq + g) * SEQ + kb * 128 + 8 * nt + 2 * tg)
                = make_float2(acc[0], acc[1]);
            *(float2*)(Sh + (size_t)(wq + g + 8) * SEQ + kb * 128 + 8 * nt + 2 * tg)
                = make_float2(acc[2], acc[3]);

            {
                const float mx = fmaxf(acc[0], acc[1]);
                const float nm = fmaxf(mloc[0], mx);
                lloc[0] = lloc[0] * __expf(mloc[0] - nm) + __expf(acc[0] - nm) + __expf(acc[1] - nm);
                mloc[0] = nm;
            }
            {
                const float mx = fmaxf(acc[2], acc[3]);
                const float nm = fmaxf(mloc[1], mx);
                lloc[1] = lloc[1] * __expf(mloc[1] - nm) + __expf(acc[2] - nm) + __expf(acc[3] - nm);
                mloc[1] = nm;
            }
        }
    }

    // ---- merge (m,l) across the quad ----
    float invl[2];
#pragma unroll
    for (int i = 0; i < 2; i++) {
#pragma unroll
        for (int off = 1; off <= 2; off <<= 1) {
            const float om = __shfl_xor_sync(0xffffffffu, mloc[i], off);
            const float ol = __shfl_xor_sync(0xffffffffu, lloc[i], off);
            const float nm = fmaxf(mloc[i], om);
            lloc[i] = lloc[i] * __expf(mloc[i] - nm) + ol * __expf(om - nm);
            mloc[i] = nm;
        }
        invl[i] = 1.f / lloc[i];
    }

    // ================= Phase 2: probabilities + PV =================
    float ctx[8][4];
#pragma unroll
    for (int nt = 0; nt < 8; nt++)
#pragma unroll
        for (int j = 0; j < 4; j++) ctx[nt][j] = 0.f;

    const int vlr = tid >> 2;            // VT-copy row 0..63
    const int vqt = tid & 3;
    for (int kb = 0; kb < 8; kb++) {
        __syncthreads();
        {   // copy VT tile: row seg = 64 uint2 = 32 uint4; 4 threads/row x 8 uint4
            const uint4* src = (const uint4*)(VTh + (size_t)vlr * (SEQ / 2) + kb * 64) + vqt * 8;
            uint4* dst = (uint4*)(sKV2 + vlr * VSTR) + vqt * 8;
#pragma unroll
            for (int i = 0; i < 8; i++) dst[i] = src[i];
        }
        __syncthreads();

#pragma unroll 1
        for (int kc = 0; kc < 8; kc++) {
            const int cbase = kb * 128 + 16 * kc;
            const float2 sa = *(const float2*)(Sh + (size_t)(wq + g) * SEQ + cbase + 2 * tg);
            const float2 sb = *(const float2*)(Sh + (size_t)(wq + g + 8) * SEQ + cbase + 2 * tg);
            const float2 sc = *(const float2*)(Sh + (size_t)(wq + g) * SEQ + cbase + 2 * tg + 8);
            const float2 sd = *(const float2*)(Sh + (size_t)(wq + g + 8) * SEQ + cbase + 2 * tg + 8);
            float2 pa, pb, pc, pd;
            pa.x = __expf(sa.x - mloc[0]) * invl[0]; pa.y = __expf(sa.y - mloc[0]) * invl[0];
            pb.x = __expf(sb.x - mloc[1]) * invl[1]; pb.y = __expf(sb.y - mloc[1]) * invl[1];
            pc.x = __expf(sc.x - mloc[0]) * invl[0]; pc.y = __expf(sc.y - mloc[0]) * invl[0];
            pd.x = __expf(sd.x - mloc[1]) * invl[1]; pd.y = __expf(sd.y - mloc[1]) * invl[1];

            if (attn_out) {
                float* ao = attn_out + ((size_t)H * SEQ + q0) * SEQ;
                *(float2*)(ao + (size_t)(wq + g) * SEQ + cbase + 2 * tg)         = pa;
                *(float2*)(ao + (size_t)(wq + g + 8) * SEQ + cbase + 2 * tg)     = pb;
                *(float2*)(ao + (size_t)(wq + g) * SEQ + cbase + 2 * tg + 8)     = pc;
                *(float2*)(ao + (size_t)(wq + g + 8) * SEQ + cbase + 2 * tg + 8) = pd;
            }

            uint32_t ah[4], al[4];
            if (pv3) {
                hilo2(pa, ah[0], al[0]); hilo2(pb, ah[1], al[1]);
                hilo2(pc, ah[2], al[2]); hilo2(pd, ah[3], al[3]);
            } else {
                ah[0] = h2pack(pa.x, pa.y); ah[1] = h2pack(pb.x, pb.y);
                ah[2] = h2pack(pc.x, pc.y); ah[3] = h2pack(pd.x, pd.y);
            }

#pragma unroll
            for (int nt = 0; nt < 8; nt++) {
                const uint2 v0 = sKV2[(8 * nt + g) * VSTR + 8 * kc + tg];
                const uint2 v1 = sKV2[(8 * nt + g) * VSTR + 8 * kc + tg + 4];
                uint32_t vh[2] = {v0.x, v1.x};
                uint32_t vl[2] = {v0.y, v1.y};
                mma_f16(ctx[nt], ah, vh);
                mma_f16(ctx[nt], ah, vl);
                if (pv3) mma_f16(ctx[nt], al, vh);
            }
        }
    }

    // ---- write ctx into interleaved ctot (row stride 128) ----
#pragma unroll
    for (int nt = 0; nt < 8; nt++) {
        const int c = ctx_off + 8 * nt + 2 * tg;
        *(float2*)(ctx_out + ((size_t)H * SEQ + q0 + wq + g) * 128 + c)
            = make_float2(ctx[nt][0], ctx[nt][1]);
        *(float2*)(ctx_out + ((size_t)H * SEQ + q0 + wq + g + 8) * 128 + c)
            = make_float2(ctx[nt][2], ctx[nt][3]);
    }
}

// ---------------------------------------------------------------------------
// Row LayerNorm over ND=2048
// ---------------------------------------------------------------------------
__global__ void ln_kernel(const float* __restrict__ X, const float* __restrict__ gamma,
                          const float* __restrict__ beta, float* __restrict__ Y)
{
    __shared__ float red[64];
    const int row = blockIdx.x;
    const float* x = X + (size_t)row * ND;
    float sum = 0.f, sq = 0.f;
    for (int i = threadIdx.x; i < ND; i += blockDim.x) {
        const float v = x[i];
        sum += v; sq += v * v;
    }
#pragma unroll
    for (int off = 16; off; off >>= 1) {
        sum += __shfl_xor_sync(0xffffffffu, sum, off);
        sq  += __shfl_xor_sync(0xffffffffu, sq, off);
    }
    const int warp = threadIdx.x >> 5, lane = threadIdx.x & 31;
    if (lane == 0) { red[warp] = sum; red[warp + 32] = sq; }
    __syncthreads();
    if (warp == 0) {
        sum = (lane < 8) ? red[lane] : 0.f;
        sq  = (lane < 8) ? red[lane + 32] : 0.f;
#pragma unroll
        for (int off = 4; off; off >>= 1) {
            sum += __shfl_xor_sync(0xffffffffu, sum, off);
            sq  += __shfl_xor_sync(0xffffffffu, sq, off);
        }
        if (lane == 0) { red[0] = sum; red[1] = sq; }
    }
    __syncthreads();
    const float mu  = red[0] * (1.f / ND);
    const float var = red[1] * (1.f / ND) - mu * mu;
    const float inv = rsqrtf(var + 1e-5f);
    float* y = Y + (size_t)row * ND;
    for (int i = threadIdx.x; i < ND; i += blockDim.x)
        y[i] = (x[i] - mu) * inv * gamma[i] + beta[i];
}

// ---------------------------------------------------------------------------
extern "C" void kernel_launch(void* const* d_in, const int* in_sizes, int n_in,
                              void* d_out, int out_size)
{
    const float* k_in  = (const float*)d_in[0];
    const float* v_in  = (const float*)d_in[1];
    const float* q_in  = (const float*)d_in[2];
    const float* r_in  = (const float*)d_in[3];
    const float* Wr    = (const float*)d_in[4];
    const float* br    = (const float*)d_in[5];
    const float* Wf    = (const float*)d_in[6];
    const float* bf    = (const float*)d_in[7];
    const float* gamma = (const float*)d_in[8];
    const float* beta  = (const float*)d_in[9];

    float* out      = (float*)d_out;
    float* y_out    = out;
    float* attn_out = out + (size_t)MROWS * ND;

    float*  rp;     cudaGetSymbolAddress((void**)&rp, g_rp);
    float*  ctot;   cudaGetSymbolAddress((void**)&ctot, g_ctot);
    float*  scores; cudaGetSymbolAddress((void**)&scores, g_scores);
    __half* rh;     cudaGetSymbolAddress((void**)&rh, g_rh);
    __half* wrh;    cudaGetSymbolAddress((void**)&wrh, g_wrh);
    __half* wfh;    cudaGetSymbolAddress((void**)&wfh, g_wfh);
    __half* ctoth;  cudaGetSymbolAddress((void**)&ctoth, g_ctoth);
    uint2*  k2;     cudaGetSymbolAddress((void**)&k2, g_k2);
    uint2*  vt2;    cudaGetSymbolAddress((void**)&vt2, g_vt2);

    cudaFuncSetAttribute(attn_f16, cudaFuncAttributeMaxDynamicSharedMemorySize, ATTN_SMEM);
    cudaFuncSetAttribute(gemm_f16, cudaFuncAttributeMaxDynamicSharedMemorySize, GEMM_SMEM);

    // 0) pre-passes
    {
        const int T = 256;
        int n;
        n = (MROWS * MD) / 4;  conv_half_kernel<<<(n + T - 1) / T, T>>>(r_in, rh, n);
        n = (ND * MD) / 4;     conv_half_kernel<<<(n + T - 1) / T, T>>>(Wr, wrh, n);
        n = (ND * ND) / 4;     conv_half_kernel<<<(n + T - 1) / T, T>>>(Wf, wfh, n);
        n = (HEADS * SEQ * DH) / 4;
        split_k_kernel<<<(n + T - 1) / T, T>>>(k_in, k2, n);
        n = HEADS * DH * (SEQ / 2);
        split_vt_kernel<<<n / T, T>>>(v_in, vt2);
    }

    // 1) rp = r @ Wr^T + br
    dim3 g1(ND / 128, MROWS / 128);
    gemm_f16<<<g1, 256, GEMM_SMEM>>>(rh, wrh, br, nullptr, rp, MROWS, ND, MD);

    // 2) pass 1: attn1 -> d_out, ctx1 -> ctot[..,0:64]  (PV x3)
    dim3 ga(SEQ / 128, HEADS);
    attn_f16<<<ga, 256, ATTN_SMEM>>>(q_in, SEQ * DH, DH, k2, vt2, scores, attn_out, ctot, 0, 1);

    // 3) pass 2: queries = ctx1 (stride 128), ctx2 -> ctot[..,64:128]  (PV x2)
    attn_f16<<<ga, 256, ATTN_SMEM>>>(ctot, SEQ * 128, 128, k2, vt2, scores, nullptr, ctot, 64, 0);

    // 3b) ctot -> fp16
    {
        const int T = 256;
        const int n = (HEADS * SEQ * 128) / 4;
        conv_half_kernel<<<(n + T - 1) / T, T>>>(ctot, ctoth, n);
    }

    // 4) x = ctot @ Wf^T + bf + rp
    gemm_f16<<<g1, 256, GEMM_SMEM>>>(ctoth, wfh, bf, rp, rp, MROWS, ND, ND);

    // 5) y = LayerNorm(x)
    ln_kernel<<<MROWS, 256>>>(rp, gamma, beta, y_out);
}